// round 14
// baseline (speedup 1.0000x reference)
#include <cuda_runtime.h>

#define B 16
#define G 5000
#define K 256
#define HID 64
#define NCHUNK 148
#define NG1 34            // genes/block in K1 (148*34 = 5032 >= 5000)
#define NG1P 36           // padded gene slots
#define GT 40             // genes per output CTA (125 CTAs * 40 = 5000)
#define NB23 141          // 16 APPNP CTAs + 125 output CTAs
#define NOUT 125

typedef unsigned long long u64;

// Scratch (no allocations; counters monotone across replays => replay-safe)
__device__ __align__(16) float g_partial[NCHUNK][B][K];  // 2.4 MB
__device__ __align__(16) float g_A2[K * K];              // A@A (256 KB)
__device__ __align__(16) float g_Z[B][K];
__device__ float g_coff[B];
__device__ u64 g_c1, g_cA2, g_c2; // epoch / A2-ready / Z-ready counters

// ---- packed fp32x2 helpers (FFMA2 is PTX-only) ----
__device__ __forceinline__ u64 pack2(float x, float y) {
    u64 r; asm("mov.b64 %0, {%1, %2};" : "=l"(r) : "f"(x), "f"(y)); return r;
}
__device__ __forceinline__ void unpack2(u64 v, float& x, float& y) {
    asm("mov.b64 {%0, %1}, %2;" : "=f"(x), "=f"(y) : "l"(v));
}
__device__ __forceinline__ void ffma2(u64& acc, u64 a, u64 b) {
    asm("fma.rn.f32x2 %0, %1, %2, %0;" : "+l"(acc) : "l"(a), "l"(b));
}
__device__ __forceinline__ u64 lds_b64(unsigned a) {
    u64 r; asm volatile("ld.shared.b64 %0, [%1];" : "=l"(r) : "r"(a)); return r;
}
__device__ __forceinline__ void lds_v2b64(unsigned a, u64& x, u64& y) {
    asm volatile("ld.shared.v2.b64 {%0, %1}, [%2];" : "=l"(x), "=l"(y) : "r"(a));
}
__device__ __forceinline__ void sts_b64(unsigned a, u64 v) {
    asm volatile("st.shared.b64 [%0], %1;" :: "r"(a), "l"(v) : "memory");
}
__device__ __forceinline__ void grid_dep_wait() {
    asm volatile("griddepcontrol.wait;" ::: "memory");
}

#define FMAXUPD(ACC, T, MV)                         \
    ACC.x = fmaxf(ACC.x, (T) * MV.x);               \
    ACC.y = fmaxf(ACC.y, (T) * MV.y);               \
    ACC.z = fmaxf(ACC.z, (T) * MV.z);               \
    ACC.w = fmaxf(ACC.w, (T) * MV.w);

// ---------------------------------------------------------------------------
// K1: max-pool (R12 verbatim). 148 blocks x 1024 threads, 1 CTA/SM.
// ---------------------------------------------------------------------------
__global__ __launch_bounds__(1024) void k1_maxpool(
    const float* __restrict__ t, const float* __restrict__ M)
{
    extern __shared__ float s1[];
    float*  ts   = s1;                         // ts4[gl][h] float4 = 576 floats
    float*  Ms   = s1 + 576;                   // [NG1P][256] = 9216
    float4* red4 = (float4*)(s1 + 576 + 9216); // [64][64] float4 = 64 KB

    const int tid = threadIdx.x;
    const int g0  = blockIdx.x * NG1;

    if (tid < NG1P * 16) {
        int gl = tid >> 4;
        int b  = tid & 15;
        int g  = g0 + gl;
        ts[gl * 16 + b] = (gl < NG1 && g < G) ? t[b * G + g] : 0.0f;
    }
    for (int i = tid; i < NG1P * 64; i += 1024) {
        int gl = i >> 6, jq = i & 63;
        int g = g0 + gl;
        float4 v = (gl < NG1 && g < G)
                 ? *(const float4*)(M + (size_t)g * K + 4 * jq)
                 : make_float4(0.f, 0.f, 0.f, 0.f);
        *(float4*)(Ms + gl * 256 + 4 * jq) = v;
    }
    __syncthreads();

    const int q4 = tid & 63;
    const int h  = (tid >> 6) & 3;
    const int ge = tid >> 8;

    const float4* MsV = (const float4*)Ms + ge * 64 + q4;
    const float4* TsV = (const float4*)ts + ge * 4 + h;

    float4 acc[4];
#pragma unroll
    for (int ii = 0; ii < 4; ii++) acc[ii] = make_float4(0.f, 0.f, 0.f, 0.f);

    float4 m  = MsV[0];
    float4 tq = TsV[0];
#pragma unroll
    for (int u = 0; u < 9; u++) {
        float4 mn, tn;
        if (u < 8) {
            mn = MsV[(u + 1) * 256];
            tn = TsV[(u + 1) * 16];
        }
        FMAXUPD(acc[0], tq.x, m)
        FMAXUPD(acc[1], tq.y, m)
        FMAXUPD(acc[2], tq.z, m)
        FMAXUPD(acc[3], tq.w, m)
        if (u < 8) { m = mn; tq = tn; }
    }

#pragma unroll
    for (int ii = 0; ii < 4; ii++)
        red4[(((ge * 4 + h) * 4 + ii) << 6) + q4] = acc[ii];
    __syncthreads();

    {
        const int q4r = tid & 63;
        const int b   = tid >> 6;
        const int hr  = b >> 2;
        const int ii  = b & 3;
        float4 a = red4[(((0 * 4 + hr) * 4 + ii) << 6) + q4r];
        float4 c = red4[(((1 * 4 + hr) * 4 + ii) << 6) + q4r];
        float4 d = red4[(((2 * 4 + hr) * 4 + ii) << 6) + q4r];
        float4 e = red4[(((3 * 4 + hr) * 4 + ii) << 6) + q4r];
        float4 r;
        r.x = fmaxf(fmaxf(a.x, c.x), fmaxf(d.x, e.x));
        r.y = fmaxf(fmaxf(a.y, c.y), fmaxf(d.y, e.y));
        r.z = fmaxf(fmaxf(a.z, c.z), fmaxf(d.z, e.z));
        r.w = fmaxf(fmaxf(a.w, c.w), fmaxf(d.w, e.w));
        *(float4*)(&g_partial[blockIdx.x][b][4 * q4r]) = r;
    }
}
#define K1_SMEM ((576 + 9216 + 64 * 64 * 4) * (int)sizeof(float))

// ---------------------------------------------------------------------------
// K23: merged. CTAs 0..15: APPNP for b = bid via A^2 double-stepping:
//   T2 = 0.09*S@A + 0.1*S (1 step, A from global/L2)
//   Z <- 0.81*Z@A^2 + T2  (5 double-steps, A^2 from smem+regs)
// CTAs 16..140: compute A^2 rows (overlaps K1), publish g_cA2; prestage;
// spin on g_c2; z_gene + MLP + store.
// All 141 CTAs co-resident (1024 thr, 87-89 KB smem => 1 CTA/SM).
// ---------------------------------------------------------------------------
// APPNP smem (floats): A2 pairs 20480 | Zs 256 | pred 1024 | Ss 256 | Ts 256
#define KA_ZS    20480
#define KA_PRED  20736
#define KA_SS    21760
#define KA_TS    22016
#define KA_FLOATS 22272

// Output smem layout (floats)
#define K3_MS     0        // [40][257] + 8 pad = 10288
#define K3_Z4     10288    // [258][4] float4 = 4128
#define K3_ZPART  14416    // [6][4][40] float4 = 3840
#define K3_WPACK  18256
#define K3_W2S    18512
#define K3_CTS    18576
#define K3_TTS    19216
#define K3_COFF   19856
#define K3_ZFIN   19872
#define K3_YPART  20512
#define K3_FLOATS 21792

#define K23_SMEM_BYTES (KA_FLOATS * (int)sizeof(float))   // 89088 (max of both)

__global__ __launch_bounds__(1024, 1) void k23(
    const float* __restrict__ A,
    const int*   __restrict__ cell_idx,
    const float* __restrict__ cell_emb,
    const float* __restrict__ W2,
    const float* __restrict__ b2,
    const float* __restrict__ ctl,
    const float* __restrict__ t,
    const float* __restrict__ M,
    const float* __restrict__ W1,
    const float* __restrict__ b1,
    float* __restrict__ out)
{
    extern __shared__ float s[];
    const int tid = threadIdx.x;
    const int bid = blockIdx.x;

    // Epoch from own arrival position (monotone counter; replay-safe).
    u64 L = 0;
    if (tid == 0) L = atomicAdd(&g_c1, 1ULL) / (u64)NB23;

    if (bid < B) {
        // ==================== APPNP path (CTAs 0..15) ====================
        float* Zs   = s + KA_ZS;
        float* pred = s + KA_PRED;
        float* Ss   = s + KA_SS;
        float* Ts   = s + KA_TS;
        const unsigned abase = (unsigned)__cvta_generic_to_shared(s);
        const unsigned zbase = abase + KA_ZS * 4;
        const int b = bid;
        const int q = tid >> 8;
        const int k = tid & 255;

        // pre-wait: cell offset (independent of everything)
        if (tid >= 992) {
            int lane = tid - 992;
            int ci = cell_idx[b];
            float v = cell_emb[ci * HID + lane] * W2[lane]
                    + cell_emb[ci * HID + 32 + lane] * W2[32 + lane];
#pragma unroll
            for (int o = 16; o > 0; o >>= 1)
                v += __shfl_down_sync(0xffffffffu, v, o);
            if (lane == 0) g_coff[b] = v + b2[0];
        }

        // wait for A^2 (published by output CTAs, ~3 us, hidden under K1)
        if (tid == 0) {
            u64 tgt = (L + 1) * (u64)NOUT;
            while (*(volatile u64*)&g_cA2 < tgt) __nanosleep(32);
            __threadfence();
        }
        __syncthreads();

        // stage A^2: register pairs j in [64q+20, 64q+64)
        u64 regA2[22];
#pragma unroll
        for (int u = 0; u < 22; u++) {
            int j0 = 64 * q + 20 + 2 * u;
            regA2[u] = pack2(g_A2[j0 * K + k], g_A2[(j0 + 1) * K + k]);
        }
        // stage A^2: smem pairs (rows r = jq*10 + jj, j = 64jq + 2jj)
        for (int i = tid; i < 40 * 256; i += 1024) {
            int r = i >> 8, kk = i & 255;
            int jq = r / 10, jj = r - 10 * jq;
            int j0 = 64 * jq + 2 * jj;
            u64 pk = pack2(g_A2[j0 * K + kk], g_A2[j0 * K + K + kk]);
            sts_b64(abase + (unsigned)(i * 8), pk);
        }

        grid_dep_wait();           // wait for K1's g_partial

        {
            float m = 0.0f;
            const float* gp = &g_partial[q * 37][b][k];
#pragma unroll
            for (int c = 0; c < 37; c++)
                m = fmaxf(m, gp[c * (B * K)]);
            pred[tid] = m;
        }
        __syncthreads();

        const float s_k = fmaxf(fmaxf(pred[k], pred[256 + k]),
                                fmaxf(pred[512 + k], pred[768 + k]));
        if (q == 0) { Zs[k] = s_k; Ss[k] = s_k; }
        __syncthreads();

        // ---- T2 step: T2 = 0.09*S@A + 0.1*S  (A from global, L2-warm) ----
        {
            float acc = 0.0f;
            const float* Ap = A + (64 * q) * K + k;      // coalesced over k
            const float* Sq = Ss + 64 * q;
#pragma unroll 8
            for (int j = 0; j < 64; j++)
                acc = fmaf(Ap[j * K], Sq[j], acc);       // Sq[j] broadcast
            pred[tid] = acc;
            __syncthreads();
            if (q == 0) {
                float v = (pred[k] + pred[256 + k]) + (pred[512 + k] + pred[768 + k]);
                Ts[k] = fmaf(0.09f, v, 0.1f * s_k);
            }
            __syncthreads();
        }

        // ---- 5 double-steps: Z <- 0.81*Z@A^2 + T2 ----
        const unsigned zA = zbase + (unsigned)(64 * q * 4);
        const unsigned zB = zA + 20 * 4;
        const unsigned aTh = abase + (unsigned)(((q * 10) * 256 + k) * 8);

#pragma unroll 1
        for (int ss = 0; ss < 5; ss++) {
            u64 acc = 0;
#pragma unroll
            for (int i = 0; i < 5; i++) {
                u64 z0, z1;
                lds_v2b64(zA + 16 * i, z0, z1);
                u64 a0 = lds_b64(aTh + (unsigned)((2 * i) * 256 * 8));
                u64 a1 = lds_b64(aTh + (unsigned)((2 * i + 1) * 256 * 8));
                ffma2(acc, a0, z0);
                ffma2(acc, a1, z1);
            }
#pragma unroll
            for (int i = 0; i < 11; i++) {
                u64 z0, z1;
                lds_v2b64(zB + 16 * i, z0, z1);
                ffma2(acc, regA2[2 * i], z0);
                ffma2(acc, regA2[2 * i + 1], z1);
            }
            float lo, hi;
            unpack2(acc, lo, hi);
            pred[tid] = lo + hi;
            __syncthreads();
            if (q == 0) {
                float v = (pred[k] + pred[256 + k]) + (pred[512 + k] + pred[768 + k]);
                Zs[k] = fmaf(0.81f, v, Ts[k]);
            }
            __syncthreads();
        }

        if (q == 0) g_Z[b][k] = Zs[k];
        __threadfence();
        __syncthreads();
        if (tid == 0) atomicAdd(&g_c2, 1ULL);    // release output CTAs
        return;
    }

    // ==================== output path (CTAs 16..140) ====================
    {
        float*  Ms     = s + K3_MS;
        float4* Z4     = (float4*)(s + K3_Z4);
        float4* zpart  = (float4*)(s + K3_ZPART);
        float4* wpack  = (float4*)(s + K3_WPACK);
        float*  W2s    = s + K3_W2S;
        float*  cts    = s + K3_CTS;
        float*  tts    = s + K3_TTS;
        float*  coffs  = s + K3_COFF;
        float*  zfin   = s + K3_ZFIN;
        float2* ypart  = (float2*)(s + K3_YPART);

        const int i0 = bid - B;
        const int g0 = i0 * GT;

        // ---- A^2 rows (before any smem staging; scratch = s[0..1024)) ----
        {
            const int lc = tid >> 8;
            const int kk = tid & 255;
            for (int row = i0; row < K; row += NOUT) {
                const float* Arow = A + row * K + 64 * lc;   // broadcast reads
                const float* Acol = A + (64 * lc) * K + kk;  // coalesced reads
                float acc = 0.0f;
#pragma unroll 8
                for (int l = 0; l < 64; l++)
                    acc = fmaf(Arow[l], Acol[l * K], acc);
                s[tid] = acc;
                __syncthreads();
                if (tid < 256)
                    g_A2[row * K + tid] =
                        (s[tid] + s[256 + tid]) + (s[512 + tid] + s[768 + tid]);
                __syncthreads();
            }
            __threadfence();
            if (tid == 0) atomicAdd(&g_cA2, 1ULL);
        }

        // ---- prestage (overlaps K1 + APPNP) ----
        for (int i = tid; i < GT * 64; i += 1024) {
            int gl = i >> 6, jq = i & 63;
            int g = g0 + gl;
            float4 v = (g < G) ? *(const float4*)(M + (size_t)g * K + 4 * jq)
                               : make_float4(0.f, 0.f, 0.f, 0.f);
            float* d = Ms + gl * 257 + 4 * jq;
            d[0] = v.x; d[1] = v.y; d[2] = v.z; d[3] = v.w;
        }
        if (tid < 8) Ms[40 * 257 + tid] = 0.0f;
        if (tid < 8) Z4[256 * 4 + tid] = make_float4(0.f, 0.f, 0.f, 0.f);
        if (tid < 64) {
            wpack[tid] = make_float4(W1[tid], W1[HID + tid], W1[2 * HID + tid], b1[tid]);
            W2s[tid]   = W2[tid];
        }
        if (tid < B * GT) {
            int bb = tid / GT, gl = tid % GT;
            int g = g0 + gl;
            cts[tid] = (g < G) ? ctl[bb * G + g] : 0.0f;
            tts[tid] = (g < G) ? t[bb * G + g] : 0.0f;
        }

        // spin until all 16 APPNP CTAs published Z (this launch's epoch)
        if (tid == 0) {
            u64 tgt = (L + 1) * (u64)B;
            while (*(volatile u64*)&g_c2 < tgt) __nanosleep(64);
            __threadfence();
        }
        __syncthreads();

        {
            int p4 = tid >> 8, j = tid & 255;
            float4 zz;
            zz.x = g_Z[4 * p4 + 0][j];
            zz.y = g_Z[4 * p4 + 1][j];
            zz.z = g_Z[4 * p4 + 2][j];
            zz.w = g_Z[4 * p4 + 3][j];
            Z4[j * 4 + p4] = zz;
        }
        if (tid < B) coffs[tid] = g_coff[tid];
        __syncthreads();

        // Phase B: partial z-dots (warp-aligned: p4 = r&3, gl = r>>2)
        if (tid < 960) {
            const int jh = tid / 160;
            const int r  = tid - jh * 160;
            const int p4 = r & 3;
            const int gl = r >> 2;
            const int j0 = jh * 43;
            const float*  Mrow = Ms + gl * 257 + j0;
            const float4* Zj   = Z4 + j0 * 4 + p4;
            float4 acc = make_float4(0.f, 0.f, 0.f, 0.f);
#pragma unroll
            for (int c = 0; c < 43; c++) {
                float  m = Mrow[c];
                float4 z = Zj[c * 4];
                acc.x = fmaf(m, z.x, acc.x);
                acc.y = fmaf(m, z.y, acc.y);
                acc.z = fmaf(m, z.z, acc.z);
                acc.w = fmaf(m, z.w, acc.w);
            }
            zpart[(jh * 4 + p4) * 40 + gl] = acc;
        }
        __syncthreads();

        // Phase C: reduce over 6 jh
        if (tid < 160) {
            int p4 = tid / 40, gl = tid - p4 * 40;
            float4 sv = make_float4(0.f, 0.f, 0.f, 0.f);
#pragma unroll
            for (int jh = 0; jh < 6; jh++) {
                float4 v = zpart[(jh * 4 + p4) * 40 + gl];
                sv.x += v.x; sv.y += v.y; sv.z += v.z; sv.w += v.w;
            }
            zfin[(4 * p4 + 0) * 40 + gl] = sv.x;
            zfin[(4 * p4 + 1) * 40 + gl] = sv.y;
            zfin[(4 * p4 + 2) * 40 + gl] = sv.z;
            zfin[(4 * p4 + 3) * 40 + gl] = sv.w;
        }
        __syncthreads();

        // Phase D: partial MLP (32 HID each)
        if (tid < 640) {
            const int jh2 = tid / 320;
            const int r   = tid - jh2 * 320;
            const int p   = r / 40;
            const int gl  = r - p * 40;
            float z0 = zfin[p * 40 + gl],  z1 = zfin[(p + 8) * 40 + gl];
            float c0 = cts[p * 40 + gl],   c1 = cts[(p + 8) * 40 + gl];
            float t0 = tts[p * 40 + gl],   t1 = tts[(p + 8) * 40 + gl];
            float y0 = 0.f, y1 = 0.f;
#pragma unroll
            for (int jj = 0; jj < 32; jj++) {
                int j = 32 * jh2 + jj;
                float4 w = wpack[j];
                float  w2 = W2s[j];
                float v0 = fmaf(c0, w.x, fmaf(t0, w.y, fmaf(z0, w.z, w.w)));
                float v1 = fmaf(c1, w.x, fmaf(t1, w.y, fmaf(z1, w.z, w.w)));
                y0 = fmaf(fmaxf(v0, 0.f), w2, y0);
                y1 = fmaf(fmaxf(v1, 0.f), w2, y1);
            }
            ypart[jh2 * 320 + r] = make_float2(y0, y1);
        }
        __syncthreads();

        // Phase E: reduce + store
        if (tid < 320) {
            int p = tid / 40, gl = tid - p * 40;
            int g = g0 + gl;
            if (g < G) {
                float2 a = ypart[tid], bb = ypart[320 + tid];
                out[p * G + g]       = (a.x + bb.x) + coffs[p];
                out[(p + 8) * G + g] = (a.y + bb.y) + coffs[p + 8];
            }
        }
    }
}

// ---------------------------------------------------------------------------
// metadata order: ctl, drug_targets, cell_idx, drug_fp, M, A, W1, b1,
//                 cell_emb, W2, b2   -> output [B, G] float32
// ---------------------------------------------------------------------------
extern "C" void kernel_launch(void* const* d_in, const int* in_sizes, int n_in,
                              void* d_out, int out_size)
{
    const float* ctl      = (const float*)d_in[0];
    const float* tgt      = (const float*)d_in[1];
    const int*   cell_idx = (const int*)  d_in[2];
    // d_in[3] = drug_fp (unused by the model)
    const float* M        = (const float*)d_in[4];
    const float* A        = (const float*)d_in[5];
    const float* W1       = (const float*)d_in[6];
    const float* b1       = (const float*)d_in[7];
    const float* cell_emb = (const float*)d_in[8];
    const float* W2       = (const float*)d_in[9];
    const float* b2       = (const float*)d_in[10];
    float* out = (float*)d_out;

    cudaFuncSetAttribute(k1_maxpool,
                         cudaFuncAttributeMaxDynamicSharedMemorySize, K1_SMEM);
    cudaFuncSetAttribute(k23,
                         cudaFuncAttributeMaxDynamicSharedMemorySize, K23_SMEM_BYTES);

    k1_maxpool<<<NCHUNK, 1024, K1_SMEM>>>(tgt, M);

    cudaLaunchAttribute pdl[1];
    pdl[0].id = cudaLaunchAttributeProgrammaticStreamSerialization;
    pdl[0].val.programmaticStreamSerializationAllowed = 1;

    cudaLaunchConfig_t cfg = {};
    cfg.gridDim = dim3(NB23, 1, 1);
    cfg.blockDim = dim3(1024, 1, 1);
    cfg.dynamicSmemBytes = K23_SMEM_BYTES;
    cfg.attrs = pdl;
    cfg.numAttrs = 1;
    cudaLaunchKernelEx(&cfg, k23, A, cell_idx, cell_emb, W2, b2,
                       ctl, tgt, M, W1, b1, out);
}

// round 15
// speedup vs baseline: 1.3268x; 1.3268x over previous
#include <cuda_runtime.h>

#define B 16
#define G 5000
#define K 256
#define HID 64
#define NCHUNK 148
#define NG1 34            // genes/block in K1 (148*34 = 5032 >= 5000)
#define NG1P 36           // padded gene slots
#define GT 40             // genes/block in K3 (125 blocks)

typedef unsigned long long u64;

// Scratch (no allocations; everything rewritten identically per launch)
__device__ __align__(16) float g_partial[NCHUNK][B][K];  // 2.4 MB
__device__ __align__(16) u64 g_Ap[128 * 256];            // (A[2p][k],A[2p+1][k])
__device__ __align__(16) u64 g_A2p[128 * 256];           // (A2[2p][k],A2[2p+1][k])
__device__ __align__(16) float g_Z[B][K];
__device__ float g_coff[B];

// ---- packed fp32x2 helpers (FFMA2 is PTX-only) ----
__device__ __forceinline__ u64 pack2(float x, float y) {
    u64 r; asm("mov.b64 %0, {%1, %2};" : "=l"(r) : "f"(x), "f"(y)); return r;
}
__device__ __forceinline__ void unpack2(u64 v, float& x, float& y) {
    asm("mov.b64 {%0, %1}, %2;" : "=f"(x), "=f"(y) : "l"(v));
}
__device__ __forceinline__ void ffma2(u64& acc, u64 a, u64 b) {
    asm("fma.rn.f32x2 %0, %1, %2, %0;" : "+l"(acc) : "l"(a), "l"(b));
}
__device__ __forceinline__ void lds_v2b64(unsigned a, u64& x, u64& y) {
    asm volatile("ld.shared.v2.b64 {%0, %1}, [%2];" : "=l"(x), "=l"(y) : "r"(a));
}
__device__ __forceinline__ void grid_dep_wait() {
    asm volatile("griddepcontrol.wait;" ::: "memory");
}

#define FMAXUPD(ACC, T, MV)                         \
    ACC.x = fmaxf(ACC.x, (T) * MV.x);               \
    ACC.y = fmaxf(ACC.y, (T) * MV.y);               \
    ACC.z = fmaxf(ACC.z, (T) * MV.z);               \
    ACC.w = fmaxf(ACC.w, (T) * MV.w);

// ---------------------------------------------------------------------------
// K1: max-pool (R12 core) + A^2/pair-packing appendix (CTAs 0..127).
// 148 blocks x 1024 threads, 1 CTA/SM.
// ---------------------------------------------------------------------------
__global__ __launch_bounds__(1024) void k1_maxpool(
    const float* __restrict__ t, const float* __restrict__ M,
    const float* __restrict__ A)
{
    extern __shared__ float s1[];
    float*  ts   = s1;                         // ts4[gl][h] float4 = 576 floats
    float*  Ms   = s1 + 576;                   // [NG1P][256] = 9216
    float4* red4 = (float4*)(s1 + 576 + 9216); // [64][64] float4 = 64 KB

    const int tid = threadIdx.x;
    const int g0  = blockIdx.x * NG1;

    if (tid < NG1P * 16) {
        int gl = tid >> 4;
        int b  = tid & 15;
        int g  = g0 + gl;
        ts[gl * 16 + b] = (gl < NG1 && g < G) ? t[b * G + g] : 0.0f;
    }
    for (int i = tid; i < NG1P * 64; i += 1024) {
        int gl = i >> 6, jq = i & 63;
        int g = g0 + gl;
        float4 v = (gl < NG1 && g < G)
                 ? *(const float4*)(M + (size_t)g * K + 4 * jq)
                 : make_float4(0.f, 0.f, 0.f, 0.f);
        *(float4*)(Ms + gl * 256 + 4 * jq) = v;
    }
    __syncthreads();

    const int q4 = tid & 63;
    const int h  = (tid >> 6) & 3;
    const int ge = tid >> 8;

    const float4* MsV = (const float4*)Ms + ge * 64 + q4;
    const float4* TsV = (const float4*)ts + ge * 4 + h;

    float4 acc[4];
#pragma unroll
    for (int ii = 0; ii < 4; ii++) acc[ii] = make_float4(0.f, 0.f, 0.f, 0.f);

    float4 m  = MsV[0];
    float4 tq = TsV[0];
#pragma unroll
    for (int u = 0; u < 9; u++) {
        float4 mn, tn;
        if (u < 8) {
            mn = MsV[(u + 1) * 256];
            tn = TsV[(u + 1) * 16];
        }
        FMAXUPD(acc[0], tq.x, m)
        FMAXUPD(acc[1], tq.y, m)
        FMAXUPD(acc[2], tq.z, m)
        FMAXUPD(acc[3], tq.w, m)
        if (u < 8) { m = mn; tq = tn; }
    }

#pragma unroll
    for (int ii = 0; ii < 4; ii++)
        red4[(((ge * 4 + h) * 4 + ii) << 6) + q4] = acc[ii];
    __syncthreads();

    {
        const int q4r = tid & 63;
        const int b   = tid >> 6;
        const int hr  = b >> 2;
        const int ii  = b & 3;
        float4 a = red4[(((0 * 4 + hr) * 4 + ii) << 6) + q4r];
        float4 c = red4[(((1 * 4 + hr) * 4 + ii) << 6) + q4r];
        float4 d = red4[(((2 * 4 + hr) * 4 + ii) << 6) + q4r];
        float4 e = red4[(((3 * 4 + hr) * 4 + ii) << 6) + q4r];
        float4 r;
        r.x = fmaxf(fmaxf(a.x, c.x), fmaxf(d.x, e.x));
        r.y = fmaxf(fmaxf(a.y, c.y), fmaxf(d.y, e.y));
        r.z = fmaxf(fmaxf(a.z, c.z), fmaxf(d.z, e.z));
        r.w = fmaxf(fmaxf(a.w, c.w), fmaxf(d.w, e.w));
        *(float4*)(&g_partial[blockIdx.x][b][4 * q4r]) = r;
    }

    // ---- A^2 rows 2c, 2c+1 + pair packing (CTAs 0..127) ----
    if (blockIdx.x < 128) {
        __syncthreads();                        // reuse ts/Ms region
        float*  As0  = s1;                      // 256
        float*  As1  = s1 + 256;                // 256
        float4* part = (float4*)(s1 + 512);     // [8][128] float4

        const int c  = blockIdx.x;
        if (tid < 256)       As0[tid]       = A[(2 * c) * K + tid];
        else if (tid < 512)  As1[tid - 256] = A[(2 * c + 1) * K + (tid - 256)];
        __syncthreads();

        {
            const int lc  = tid >> 7;           // 0..7 (l-range of 32)
            const int kk2 = tid & 127;          // k-pair index
            float2 a0 = make_float2(0.f, 0.f);
            float2 a1 = make_float2(0.f, 0.f);
#pragma unroll 8
            for (int u = 0; u < 32; u++) {
                int l = 32 * lc + u;
                float2 av = *(const float2*)(A + l * K + 2 * kk2);
                float w0 = As0[l], w1 = As1[l];
                a0.x = fmaf(w0, av.x, a0.x);
                a0.y = fmaf(w0, av.y, a0.y);
                a1.x = fmaf(w1, av.x, a1.x);
                a1.y = fmaf(w1, av.y, a1.y);
            }
            part[lc * 128 + kk2] = make_float4(a0.x, a0.y, a1.x, a1.y);
        }
        __syncthreads();

        if (tid < 128) {
            float4 sacc = make_float4(0.f, 0.f, 0.f, 0.f);
#pragma unroll
            for (int lc = 0; lc < 8; lc++) {
                float4 v = part[lc * 128 + tid];
                sacc.x += v.x; sacc.y += v.y; sacc.z += v.z; sacc.w += v.w;
            }
            g_A2p[c * 256 + 2 * tid]     = pack2(sacc.x, sacc.z);
            g_A2p[c * 256 + 2 * tid + 1] = pack2(sacc.y, sacc.w);
        } else if (tid >= 512 && tid < 768) {
            int k = tid - 512;
            g_Ap[c * 256 + k] = pack2(As0[k], As1[k]);
        }
    }
}
#define K1_SMEM ((576 + 9216 + 64 * 64 * 4) * (int)sizeof(float))

// ---------------------------------------------------------------------------
// K2: APPNP via A^2 double-stepping, all matrix reads from L2 (pair-packed).
// 16 blocks x 1024 threads. Thread (q = tid>>8, k = tid&255) owns j-pairs
// p in [32q, 32q+32): A2 pairs 10..31 cached in regs, rest read per step.
// Sequence: Z1 = 0.9*S@A + 0.1*S; T2 = 0.1*Z1 + 0.09*S;
//           4x (Z <- 0.81*Z@A2 + T2);  Z10 = 0.9*Z9@A + 0.1*S.
// ---------------------------------------------------------------------------
__global__ __launch_bounds__(1024, 1) void k2_appnp(
    const int*   __restrict__ cell_idx,
    const float* __restrict__ cell_emb,
    const float* __restrict__ W2,
    const float* __restrict__ b2)
{
    __shared__ __align__(16) float Zs[256];
    __shared__ float Ss[256], T2s[256];
    __shared__ float pred[1024];

    const int tid = threadIdx.x;
    const int b   = blockIdx.x;
    const int q   = tid >> 8;
    const int k   = tid & 255;

    // pre-wait: cell offset (independent of K1)
    if (tid >= 992) {
        int lane = tid - 992;
        int ci = cell_idx[b];
        float v = cell_emb[ci * HID + lane] * W2[lane]
                + cell_emb[ci * HID + 32 + lane] * W2[32 + lane];
#pragma unroll
        for (int o = 16; o > 0; o >>= 1)
            v += __shfl_down_sync(0xffffffffu, v, o);
        if (lane == 0) g_coff[b] = v + b2[0];
    }

    grid_dep_wait();    // K1 done: g_partial, g_Ap, g_A2p valid

    // register-cached A2 pairs p = 32q+10 .. 32q+31
    u64 regA2[22];
#pragma unroll
    for (int u = 0; u < 22; u++)
        regA2[u] = g_A2p[(32 * q + 10 + u) * 256 + k];

    // t_mod reduction
    {
        float mv = 0.0f;
        const float* gp = &g_partial[q * 37][b][k];
#pragma unroll
        for (int c = 0; c < 37; c++)
            mv = fmaxf(mv, gp[c * (B * K)]);
        pred[tid] = mv;
    }
    __syncthreads();
    const float s_k = fmaxf(fmaxf(pred[k], pred[256 + k]),
                            fmaxf(pred[512 + k], pred[768 + k]));
    if (q == 0) { Ss[k] = s_k; Zs[k] = s_k; }
    __syncthreads();

    const unsigned zaddr = (unsigned)__cvta_generic_to_shared(Zs) + 256 * q;
    const u64* ApQ  = g_Ap  + (32 * q) * 256 + k;
    const u64* A2Q  = g_A2p + (32 * q) * 256 + k;

    // ---- Step 1: Z1 = 0.9*S@A + 0.1*S;  T2 = 0.1*Z1 + 0.09*S ----
    {
        u64 acc = 0;
#pragma unroll
        for (int i = 0; i < 16; i++) {
            u64 z0, z1;
            lds_v2b64(zaddr + 16 * i, z0, z1);
            ffma2(acc, ApQ[(2 * i) << 8], z0);
            ffma2(acc, ApQ[(2 * i + 1) << 8], z1);
        }
        float lo, hi;
        unpack2(acc, lo, hi);
        pred[tid] = lo + hi;
        __syncthreads();
        if (q == 0) {
            float v = (pred[k] + pred[256 + k]) + (pred[512 + k] + pred[768 + k]);
            float z1v = fmaf(0.9f, v, 0.1f * Ss[k]);
            Zs[k]  = z1v;
            T2s[k] = fmaf(0.1f, z1v, 0.09f * Ss[k]);
        }
        __syncthreads();
    }

    // ---- 4 double-steps: Z <- 0.81*Z@A2 + T2 ----
#pragma unroll 1
    for (int ss = 0; ss < 4; ss++) {
        u64 acc = 0;
#pragma unroll
        for (int i = 0; i < 5; i++) {          // L2 pairs 0..9
            u64 z0, z1;
            lds_v2b64(zaddr + 16 * i, z0, z1);
            ffma2(acc, A2Q[(2 * i) << 8], z0);
            ffma2(acc, A2Q[(2 * i + 1) << 8], z1);
        }
#pragma unroll
        for (int i = 0; i < 11; i++) {         // reg pairs 10..31
            u64 z0, z1;
            lds_v2b64(zaddr + 80 + 16 * i, z0, z1);
            ffma2(acc, regA2[2 * i], z0);
            ffma2(acc, regA2[2 * i + 1], z1);
        }
        float lo, hi;
        unpack2(acc, lo, hi);
        pred[tid] = lo + hi;
        __syncthreads();
        if (q == 0) {
            float v = (pred[k] + pred[256 + k]) + (pred[512 + k] + pred[768 + k]);
            Zs[k] = fmaf(0.81f, v, T2s[k]);
        }
        __syncthreads();
    }

    // ---- Final step: Z10 = 0.9*Z9@A + 0.1*S ----
    {
        u64 acc = 0;
#pragma unroll
        for (int i = 0; i < 16; i++) {
            u64 z0, z1;
            lds_v2b64(zaddr + 16 * i, z0, z1);
            ffma2(acc, ApQ[(2 * i) << 8], z0);
            ffma2(acc, ApQ[(2 * i + 1) << 8], z1);
        }
        float lo, hi;
        unpack2(acc, lo, hi);
        pred[tid] = lo + hi;
        __syncthreads();
        if (q == 0) {
            float v = (pred[k] + pred[256 + k]) + (pred[512 + k] + pred[768 + k]);
            g_Z[b][k] = fmaf(0.9f, v, 0.1f * Ss[k]);
        }
    }
}

// ---------------------------------------------------------------------------
// K3: z_gene + MLP + out (R12 verbatim). 125 blocks x 1024 threads.
// ---------------------------------------------------------------------------
#define K3_MS     0
#define K3_Z4     10280
#define K3_ZPART  14376
#define K3_WPACK  18216
#define K3_W2S    18472
#define K3_CTS    18536
#define K3_TTS    19176
#define K3_COFF   19816
#define K3_ZFIN   19832
#define K3_YPART  20472
#define K3_FLOATS 21752

__global__ __launch_bounds__(1024) void k3_out(
    const float* __restrict__ ctl,
    const float* __restrict__ t,
    const float* __restrict__ M,
    const float* __restrict__ W1,
    const float* __restrict__ b1,
    const float* __restrict__ W2,
    float* __restrict__ out)
{
    extern __shared__ float s3[];
    float*  Ms     = s3 + K3_MS;
    float4* Z4     = (float4*)(s3 + K3_Z4);
    float4* zpart  = (float4*)(s3 + K3_ZPART);
    float4* wpack  = (float4*)(s3 + K3_WPACK);
    float*  W2s    = s3 + K3_W2S;
    float*  cts    = s3 + K3_CTS;
    float*  tts    = s3 + K3_TTS;
    float*  coffs  = s3 + K3_COFF;
    float*  zfin   = s3 + K3_ZFIN;
    float2* ypart  = (float2*)(s3 + K3_YPART);

    const int tid = threadIdx.x;
    const int g0  = blockIdx.x * GT;

    for (int i = tid; i < GT * 64; i += 1024) {
        int gl = i >> 6, jq = i & 63;
        int g = g0 + gl;
        float4 v = (g < G) ? *(const float4*)(M + (size_t)g * K + 4 * jq)
                           : make_float4(0.f, 0.f, 0.f, 0.f);
        float* d = Ms + gl * 257 + 4 * jq;
        d[0] = v.x; d[1] = v.y; d[2] = v.z; d[3] = v.w;
    }
    if (tid < 64) {
        wpack[tid] = make_float4(W1[tid], W1[HID + tid], W1[2 * HID + tid], b1[tid]);
        W2s[tid]   = W2[tid];
    }
    if (tid < B * GT) {
        int bb = tid / GT, gl = tid % GT;
        int g = g0 + gl;
        cts[tid] = (g < G) ? ctl[bb * G + g] : 0.0f;
        tts[tid] = (g < G) ? t[bb * G + g] : 0.0f;
    }

    grid_dep_wait();

    {
        int p4 = tid >> 8, j = tid & 255;
        float4 zz;
        zz.x = g_Z[4 * p4 + 0][j];
        zz.y = g_Z[4 * p4 + 1][j];
        zz.z = g_Z[4 * p4 + 2][j];
        zz.w = g_Z[4 * p4 + 3][j];
        Z4[j * 4 + p4] = zz;
    }
    if (tid < B) coffs[tid] = g_coff[tid];
    __syncthreads();

    if (tid < 960) {
        const int jh = tid / 160;
        const int r  = tid - jh * 160;
        const int p4 = r / 40;
        const int gl = r - p4 * 40;
        const int j0 = (jh <= 4) ? jh * 43 : 214;
        const int j1 = (jh <= 3) ? j0 + 43 : j0 + 42;
        const float* Mrow = Ms + gl * 257;
        float4 acc = make_float4(0.f, 0.f, 0.f, 0.f);
        for (int j = j0; j < j1; j++) {
            float  m = Mrow[j];
            float4 z = Z4[j * 4 + p4];
            acc.x = fmaf(m, z.x, acc.x);
            acc.y = fmaf(m, z.y, acc.y);
            acc.z = fmaf(m, z.z, acc.z);
            acc.w = fmaf(m, z.w, acc.w);
        }
        zpart[(jh * 4 + p4) * 40 + gl] = acc;
    }
    __syncthreads();

    if (tid < 160) {
        int p4 = tid / 40, gl = tid - p4 * 40;
        float4 s = make_float4(0.f, 0.f, 0.f, 0.f);
#pragma unroll
        for (int jh = 0; jh < 6; jh++) {
            float4 v = zpart[(jh * 4 + p4) * 40 + gl];
            s.x += v.x; s.y += v.y; s.z += v.z; s.w += v.w;
        }
        zfin[(4 * p4 + 0) * 40 + gl] = s.x;
        zfin[(4 * p4 + 1) * 40 + gl] = s.y;
        zfin[(4 * p4 + 2) * 40 + gl] = s.z;
        zfin[(4 * p4 + 3) * 40 + gl] = s.w;
    }
    __syncthreads();

    if (tid < 640) {
        const int jh2 = tid / 320;
        const int r   = tid - jh2 * 320;
        const int p   = r / 40;
        const int gl  = r - p * 40;
        float z0 = zfin[p * 40 + gl],  z1 = zfin[(p + 8) * 40 + gl];
        float c0 = cts[p * 40 + gl],   c1 = cts[(p + 8) * 40 + gl];
        float t0 = tts[p * 40 + gl],   t1 = tts[(p + 8) * 40 + gl];
        float y0 = 0.f, y1 = 0.f;
#pragma unroll
        for (int jj = 0; jj < 32; jj++) {
            int j = 32 * jh2 + jj;
            float4 w = wpack[j];
            float  w2 = W2s[j];
            float v0 = fmaf(c0, w.x, fmaf(t0, w.y, fmaf(z0, w.z, w.w)));
            float v1 = fmaf(c1, w.x, fmaf(t1, w.y, fmaf(z1, w.z, w.w)));
            y0 = fmaf(fmaxf(v0, 0.f), w2, y0);
            y1 = fmaf(fmaxf(v1, 0.f), w2, y1);
        }
        ypart[jh2 * 320 + r] = make_float2(y0, y1);
    }
    __syncthreads();

    if (tid < 320) {
        int p = tid / 40, gl = tid - p * 40;
        int g = g0 + gl;
        if (g < G) {
            float2 a = ypart[tid], bb = ypart[320 + tid];
            out[p * G + g]       = (a.x + bb.x) + coffs[p];
            out[(p + 8) * G + g] = (a.y + bb.y) + coffs[p + 8];
        }
    }
}
#define K3_SMEM (K3_FLOATS * (int)sizeof(float))

// ---------------------------------------------------------------------------
// metadata order: ctl, drug_targets, cell_idx, drug_fp, M, A, W1, b1,
//                 cell_emb, W2, b2   -> output [B, G] float32
// ---------------------------------------------------------------------------
extern "C" void kernel_launch(void* const* d_in, const int* in_sizes, int n_in,
                              void* d_out, int out_size)
{
    const float* ctl      = (const float*)d_in[0];
    const float* tgt      = (const float*)d_in[1];
    const int*   cell_idx = (const int*)  d_in[2];
    // d_in[3] = drug_fp (unused by the model)
    const float* M        = (const float*)d_in[4];
    const float* A        = (const float*)d_in[5];
    const float* W1       = (const float*)d_in[6];
    const float* b1       = (const float*)d_in[7];
    const float* cell_emb = (const float*)d_in[8];
    const float* W2       = (const float*)d_in[9];
    const float* b2       = (const float*)d_in[10];
    float* out = (float*)d_out;

    cudaFuncSetAttribute(k1_maxpool,
                         cudaFuncAttributeMaxDynamicSharedMemorySize, K1_SMEM);
    cudaFuncSetAttribute(k3_out,
                         cudaFuncAttributeMaxDynamicSharedMemorySize, K3_SMEM);

    k1_maxpool<<<NCHUNK, 1024, K1_SMEM>>>(tgt, M, A);

    cudaLaunchAttribute pdl[1];
    pdl[0].id = cudaLaunchAttributeProgrammaticStreamSerialization;
    pdl[0].val.programmaticStreamSerializationAllowed = 1;

    {
        cudaLaunchConfig_t cfg = {};
        cfg.gridDim = dim3(B, 1, 1);
        cfg.blockDim = dim3(1024, 1, 1);
        cfg.dynamicSmemBytes = 0;
        cfg.attrs = pdl;
        cfg.numAttrs = 1;
        cudaLaunchKernelEx(&cfg, k2_appnp, cell_idx, cell_emb, W2, b2);
    }
    {
        cudaLaunchConfig_t cfg = {};
        cfg.gridDim = dim3((G + GT - 1) / GT, 1, 1);   // 125
        cfg.blockDim = dim3(1024, 1, 1);
        cfg.dynamicSmemBytes = K3_SMEM;
        cfg.attrs = pdl;
        cfg.numAttrs = 1;
        cudaLaunchKernelEx(&cfg, k3_out, ctl, tgt, M, W1, b1, W2, out);
    }
}